// round 1
// baseline (speedup 1.0000x reference)
#include <cuda_runtime.h>
#include <cstdint>

// Problem constants (fixed shapes for this problem instance)
#define B_  2
#define N_  6
#define Q_  900
#define C_  256
#define H_  116
#define W_  200
#define HW_ (H_ * W_)      // 23200
#define EPS_ 1e-5f
#define BQ_ (B_ * Q_)      // 1800
#define BNQ_ (B_ * N_ * Q_) // 10800

// Scratch (no dynamic allocation allowed)
__device__ float4 g_w[BQ_ * N_];     // weights per (b,q,n): 4 corners, premultiplied valid/N
__device__ int4   g_idx[BQ_ * N_];   // clamped linear pixel indices per corner
__device__ float  g_agg[BQ_ * C_];   // mean-aggregated features before output projection

// ---------------------------------------------------------------------------
// Kernel 1: project reference points -> bilinear weights + indices
// one thread per (b,q,n)
// ---------------------------------------------------------------------------
__global__ void proj_kernel(const float* __restrict__ ref_pts,   // (B,Q,3)
                            const float* __restrict__ lidar2img) // (B,N,4,4)
{
    int t = blockIdx.x * blockDim.x + threadIdx.x;
    if (t >= BNQ_) return;
    int n = t % N_;
    int r = t / N_;
    int q = r % Q_;
    int b = r / Q_;

    const float* rp = ref_pts + ((size_t)b * Q_ + q) * 3;
    float px = rp[0], py = rp[1], pz = rp[2];

    const float* M = lidar2img + ((size_t)b * N_ + n) * 16;
    float xc = M[0]  * px + M[1]  * py + M[2]  * pz + M[3];
    float yc = M[4]  * px + M[5]  * py + M[6]  * pz + M[7];
    float zc = M[8]  * px + M[9]  * py + M[10] * pz + M[11];

    float denom = fabsf(zc) + EPS_;
    float x2d = xc / denom;
    float y2d = yc / denom;

    float gx = x2d / (float)(W_ - 1) * 2.0f - 1.0f;
    float gy = y2d / (float)(H_ - 1) * 2.0f - 1.0f;

    bool front = zc > EPS_;
    bool in_img = fmaxf(fabsf(gx), fabsf(gy)) <= 1.0f;
    float vv = (front && in_img) ? (1.0f / (float)N_) : 0.0f;

    // grid_sample align_corners=False coords
    float x = ((gx + 1.0f) * (float)W_ - 1.0f) * 0.5f;
    float y = ((gy + 1.0f) * (float)H_ - 1.0f) * 0.5f;
    // clamp to keep int conversion sane; invalid points have vv = 0 anyway
    x = fminf(fmaxf(x, -100.0f), (float)(W_ + 100));
    y = fminf(fmaxf(y, -100.0f), (float)(H_ + 100));

    float x0f = floorf(x), y0f = floorf(y);
    float wx = x - x0f, wy = y - y0f;
    int x0 = (int)x0f, y0 = (int)y0f;
    int x1 = x0 + 1,   y1 = y0 + 1;

    float v00 = (x0 >= 0 && x0 < W_ && y0 >= 0 && y0 < H_) ? 1.0f : 0.0f;
    float v10 = (x1 >= 0 && x1 < W_ && y0 >= 0 && y0 < H_) ? 1.0f : 0.0f;
    float v01 = (x0 >= 0 && x0 < W_ && y1 >= 0 && y1 < H_) ? 1.0f : 0.0f;
    float v11 = (x1 >= 0 && x1 < W_ && y1 >= 0 && y1 < H_) ? 1.0f : 0.0f;

    float4 w;
    w.x = (1.0f - wx) * (1.0f - wy) * v00 * vv;
    w.y = wx          * (1.0f - wy) * v10 * vv;
    w.z = (1.0f - wx) * wy          * v01 * vv;
    w.w = wx          * wy          * v11 * vv;

    int cx0 = min(max(x0, 0), W_ - 1);
    int cx1 = min(max(x1, 0), W_ - 1);
    int cy0 = min(max(y0, 0), H_ - 1);
    int cy1 = min(max(y1, 0), H_ - 1);

    int4 idx;
    idx.x = cy0 * W_ + cx0;
    idx.y = cy0 * W_ + cx1;
    idx.z = cy1 * W_ + cx0;
    idx.w = cy1 * W_ + cx1;

    // layout (b, q, n)
    int p = (b * Q_ + q) * N_ + n;
    g_w[p] = w;
    g_idx[p] = idx;
}

// ---------------------------------------------------------------------------
// Kernel 2: bilinear gather + mean over cameras
// one block per (b,q), one thread per channel c
// ---------------------------------------------------------------------------
__global__ void gather_kernel(const float* __restrict__ feats) // (B,N,C,H,W)
{
    __shared__ float4 sw[N_];
    __shared__ int4   sidx[N_];

    int bq = blockIdx.x;          // 0..1799
    int c  = threadIdx.x;         // 0..255
    int b  = bq / Q_;

    if (threadIdx.x < N_) {
        sw[threadIdx.x]   = g_w[bq * N_ + threadIdx.x];
        sidx[threadIdx.x] = g_idx[bq * N_ + threadIdx.x];
    }
    __syncthreads();

    float acc = 0.0f;
#pragma unroll
    for (int n = 0; n < N_; n++) {
        float4 w = sw[n];
        if (w.x == 0.0f && w.y == 0.0f && w.z == 0.0f && w.w == 0.0f) continue;
        int4 id = sidx[n];
        const float* p = feats + ((size_t)(b * N_ + n) * C_ + c) * HW_;
        acc = fmaf(w.x, __ldg(p + id.x), acc);
        acc = fmaf(w.y, __ldg(p + id.y), acc);
        acc = fmaf(w.z, __ldg(p + id.z), acc);
        acc = fmaf(w.w, __ldg(p + id.w), acc);
    }
    g_agg[(size_t)bq * C_ + c] = acc;
}

// ---------------------------------------------------------------------------
// Kernel 3: out = agg @ W_out^T + b_out   (M=1800, N=256, K=256)
// tiled SGEMM: 64x64 block tile, BK=16, 4x4 thread tile, 256 threads
// ---------------------------------------------------------------------------
#define BM 64
#define BN 64
#define BK 16
__global__ __launch_bounds__(256) void gemm_kernel(const float* __restrict__ Wm,  // (256,256) row-major, K-contig
                                                   const float* __restrict__ bias,
                                                   float* __restrict__ out)       // (1800,256)
{
    __shared__ float As[BK][BM];
    __shared__ float Bs[BK][BN];

    const int M = BQ_;
    int t = threadIdx.x;
    int tn = t % 16;   // col group
    int tm = t / 16;   // row group

    int bM = blockIdx.x * BM;
    int bN = blockIdx.y * BN;

    float acc[4][4];
#pragma unroll
    for (int i = 0; i < 4; i++)
#pragma unroll
        for (int j = 0; j < 4; j++) acc[i][j] = 0.0f;

    // loader mapping: thread t loads one float4: row = t/4, k4 = t%4
    int lrow = t >> 2;
    int lk   = (t & 3) * 4;

    for (int k0 = 0; k0 < C_; k0 += BK) {
        // load A tile (agg) 64x16, guarded on M
        {
            int gm = bM + lrow;
            float4 v = make_float4(0.f, 0.f, 0.f, 0.f);
            if (gm < M)
                v = *reinterpret_cast<const float4*>(&g_agg[(size_t)gm * C_ + k0 + lk]);
            As[lk + 0][lrow] = v.x;
            As[lk + 1][lrow] = v.y;
            As[lk + 2][lrow] = v.z;
            As[lk + 3][lrow] = v.w;
        }
        // load B tile (W_out) 64x16 (N=256 divisible, no guard)
        {
            int gn = bN + lrow;
            float4 v = *reinterpret_cast<const float4*>(&Wm[(size_t)gn * C_ + k0 + lk]);
            Bs[lk + 0][lrow] = v.x;
            Bs[lk + 1][lrow] = v.y;
            Bs[lk + 2][lrow] = v.z;
            Bs[lk + 3][lrow] = v.w;
        }
        __syncthreads();

#pragma unroll
        for (int kk = 0; kk < BK; kk++) {
            float4 a = *reinterpret_cast<const float4*>(&As[kk][tm * 4]);
            float4 bv = *reinterpret_cast<const float4*>(&Bs[kk][tn * 4]);
            float av[4] = {a.x, a.y, a.z, a.w};
            float bb[4] = {bv.x, bv.y, bv.z, bv.w};
#pragma unroll
            for (int i = 0; i < 4; i++)
#pragma unroll
                for (int j = 0; j < 4; j++)
                    acc[i][j] = fmaf(av[i], bb[j], acc[i][j]);
        }
        __syncthreads();
    }

#pragma unroll
    for (int i = 0; i < 4; i++) {
        int gm = bM + tm * 4 + i;
        if (gm >= M) continue;
#pragma unroll
        for (int j = 0; j < 4; j++) {
            int gn = bN + tn * 4 + j;
            out[(size_t)gm * C_ + gn] = acc[i][j] + bias[gn];
        }
    }
}

// ---------------------------------------------------------------------------
// launch
// inputs: 0=query (unused), 1=reference_points, 2=image_features,
//         3=lidar2img, 4=W_out, 5=b_out; output float32 (B,Q,C)
// ---------------------------------------------------------------------------
extern "C" void kernel_launch(void* const* d_in, const int* in_sizes, int n_in,
                              void* d_out, int out_size)
{
    const float* ref_pts   = (const float*)d_in[1];
    const float* feats     = (const float*)d_in[2];
    const float* lidar2img = (const float*)d_in[3];
    const float* Wm        = (const float*)d_in[4];
    const float* bias      = (const float*)d_in[5];
    float* out = (float*)d_out;

    proj_kernel<<<(BNQ_ + 255) / 256, 256>>>(ref_pts, lidar2img);
    gather_kernel<<<BQ_, C_>>>(feats);
    dim3 gg((BQ_ + BM - 1) / BM, C_ / BN);
    gemm_kernel<<<gg, 256>>>(Wm, bias, out);
}

// round 2
// speedup vs baseline: 1.1826x; 1.1826x over previous
#include <cuda_runtime.h>
#include <cstdint>

// Problem constants (fixed shapes)
#define B_  2
#define N_  6
#define Q_  900
#define C_  256
#define H_  116
#define W_  200
#define HW_ (H_ * W_)       // 23200, divisible by 4
#define EPS_ 1e-5f
#define BQ_ (B_ * Q_)       // 1800

// Scratch (no dynamic allocation allowed)
__device__ float g_agg[BQ_ * C_];   // mean-aggregated features before output projection

// Uniform-index select from float4 (s is warp-uniform -> predicated SELs)
__device__ __forceinline__ float sel4(float4 f, int s) {
    float v = f.x;
    if (s == 1) v = f.y;
    else if (s == 2) v = f.z;
    else if (s == 3) v = f.w;
    return v;
}

// ---------------------------------------------------------------------------
// Fused kernel: projection (threads 0..5) + bilinear gather + camera mean
// one block per (b,q), one thread per channel c
// ---------------------------------------------------------------------------
__global__ __launch_bounds__(C_) void gather_kernel(
    const float* __restrict__ feats,     // (B,N,C,H,W)
    const float* __restrict__ ref_pts,   // (B,Q,3)
    const float* __restrict__ lidar2img) // (B,N,4,4)
{
    __shared__ float4 sw[N_];   // weights: (wl_top, wr_top, wl_bot, wr_bot) * valid/N
    __shared__ int4   sb[N_];   // {base_top, base_bot, s0|(s1<<8), valid}

    int bq  = blockIdx.x;       // 0..1799
    int b   = bq / Q_;
    int q   = bq % Q_;
    int tid = threadIdx.x;      // channel

    if (tid < N_) {
        int n = tid;
        const float* rp = ref_pts + ((size_t)b * Q_ + q) * 3;
        float px = rp[0], py = rp[1], pz = rp[2];

        const float* M = lidar2img + ((size_t)b * N_ + n) * 16;
        float xc = M[0]  * px + M[1]  * py + M[2]  * pz + M[3];
        float yc = M[4]  * px + M[5]  * py + M[6]  * pz + M[7];
        float zc = M[8]  * px + M[9]  * py + M[10] * pz + M[11];

        float denom = fabsf(zc) + EPS_;
        float x2d = xc / denom;
        float y2d = yc / denom;

        float gx = x2d / (float)(W_ - 1) * 2.0f - 1.0f;
        float gy = y2d / (float)(H_ - 1) * 2.0f - 1.0f;

        bool front  = zc > EPS_;
        bool in_img = fmaxf(fabsf(gx), fabsf(gy)) <= 1.0f;
        int  valid  = (front && in_img) ? 1 : 0;
        float vv    = valid ? (1.0f / (float)N_) : 0.0f;

        // grid_sample align_corners=False coords
        float x = ((gx + 1.0f) * (float)W_ - 1.0f) * 0.5f;
        float y = ((gy + 1.0f) * (float)H_ - 1.0f) * 0.5f;
        x = fminf(fmaxf(x, -100.0f), (float)(W_ + 100));
        y = fminf(fmaxf(y, -100.0f), (float)(H_ + 100));

        float x0f = floorf(x), y0f = floorf(y);
        float wx = x - x0f, wy = y - y0f;
        int x0 = (int)x0f, y0 = (int)y0f;
        int x1 = x0 + 1,   y1 = y0 + 1;

        float v00 = (x0 >= 0 && x0 < W_ && y0 >= 0 && y0 < H_) ? 1.0f : 0.0f;
        float v10 = (x1 >= 0 && x1 < W_ && y0 >= 0 && y0 < H_) ? 1.0f : 0.0f;
        float v01 = (x0 >= 0 && x0 < W_ && y1 >= 0 && y1 < H_) ? 1.0f : 0.0f;
        float v11 = (x1 >= 0 && x1 < W_ && y1 >= 0 && y1 < H_) ? 1.0f : 0.0f;

        float4 w;
        w.x = (1.0f - wx) * (1.0f - wy) * v00 * vv;  // top-left
        w.y = wx          * (1.0f - wy) * v10 * vv;  // top-right
        w.z = (1.0f - wx) * wy          * v01 * vv;  // bottom-left
        w.w = wx          * wy          * v11 * vv;  // bottom-right

        int cx0 = min(max(x0, 0), W_ - 1);
        int cx1 = min(max(x1, 0), W_ - 1);
        int cy0 = min(max(y0, 0), H_ - 1);
        int cy1 = min(max(y1, 0), H_ - 1);

        int i0 = cy0 * W_ + cx0;        // top-left clamped linear idx
        int i1 = cy0 * W_ + cx1;        // top-right (== i0 or i0+1)
        int j0 = cy1 * W_ + cx0;        // bottom-left (same alignment: W%4==0)

        int base_t = i0 & ~3;
        int s0 = i0 - base_t;           // 0..3
        int s1 = i1 - base_t;           // s0 or s0+1 (can be 4)
        int base_b = j0 - s0;

        sw[n] = w;
        sb[n] = make_int4(base_t, base_b, s0 | (s1 << 8), valid);
    }
    __syncthreads();

    float acc = 0.0f;
#pragma unroll
    for (int n = 0; n < N_; n++) {
        int4 ib = sb[n];
        if (!ib.w) continue;            // uniform branch: camera invalid
        float4 w = sw[n];
        const float* p = feats + ((size_t)((b * N_ + n) * C_) + tid) * HW_;

        float4 t0 = *reinterpret_cast<const float4*>(p + ib.x);
        float4 b0 = *reinterpret_cast<const float4*>(p + ib.y);

        int s0 = ib.z & 0xff;
        int s1 = ib.z >> 8;

        float vt0 = sel4(t0, s0);
        float vb0 = sel4(b0, s0);
        float vt1, vb1;
        if (s1 < 4) {                   // uniform branch (75% taken)
            vt1 = sel4(t0, s1);
            vb1 = sel4(b0, s1);
        } else {                        // right pixel spills into next float4
            vt1 = __ldg(p + ib.x + 4);
            vb1 = __ldg(p + ib.y + 4);
        }
        acc = fmaf(w.x, vt0, acc);
        acc = fmaf(w.y, vt1, acc);
        acc = fmaf(w.z, vb0, acc);
        acc = fmaf(w.w, vb1, acc);
    }
    g_agg[(size_t)bq * C_ + tid] = acc;
}

// ---------------------------------------------------------------------------
// out = agg @ W_out^T + b_out   (M=1800, N=256, K=256)
// tiled SGEMM: 64x64 block tile, BK=16, 4x4 thread tile, 256 threads
// ---------------------------------------------------------------------------
#define BM 64
#define BN 64
#define BK 16
__global__ __launch_bounds__(256) void gemm_kernel(const float* __restrict__ Wm,   // (256,256) row-major
                                                   const float* __restrict__ bias,
                                                   float* __restrict__ out)        // (1800,256)
{
    __shared__ float As[BK][BM];
    __shared__ float Bs[BK][BN];

    const int M = BQ_;
    int t = threadIdx.x;
    int tn = t % 16;
    int tm = t / 16;

    int bM = blockIdx.x * BM;
    int bN = blockIdx.y * BN;

    float acc[4][4];
#pragma unroll
    for (int i = 0; i < 4; i++)
#pragma unroll
        for (int j = 0; j < 4; j++) acc[i][j] = 0.0f;

    int lrow = t >> 2;
    int lk   = (t & 3) * 4;

    for (int k0 = 0; k0 < C_; k0 += BK) {
        {
            int gm = bM + lrow;
            float4 v = make_float4(0.f, 0.f, 0.f, 0.f);
            if (gm < M)
                v = *reinterpret_cast<const float4*>(&g_agg[(size_t)gm * C_ + k0 + lk]);
            As[lk + 0][lrow] = v.x;
            As[lk + 1][lrow] = v.y;
            As[lk + 2][lrow] = v.z;
            As[lk + 3][lrow] = v.w;
        }
        {
            int gn = bN + lrow;
            float4 v = *reinterpret_cast<const float4*>(&Wm[(size_t)gn * C_ + k0 + lk]);
            Bs[lk + 0][lrow] = v.x;
            Bs[lk + 1][lrow] = v.y;
            Bs[lk + 2][lrow] = v.z;
            Bs[lk + 3][lrow] = v.w;
        }
        __syncthreads();

#pragma unroll
        for (int kk = 0; kk < BK; kk++) {
            float4 a  = *reinterpret_cast<const float4*>(&As[kk][tm * 4]);
            float4 bv = *reinterpret_cast<const float4*>(&Bs[kk][tn * 4]);
            float av[4] = {a.x, a.y, a.z, a.w};
            float bb[4] = {bv.x, bv.y, bv.z, bv.w};
#pragma unroll
            for (int i = 0; i < 4; i++)
#pragma unroll
                for (int j = 0; j < 4; j++)
                    acc[i][j] = fmaf(av[i], bb[j], acc[i][j]);
        }
        __syncthreads();
    }

#pragma unroll
    for (int i = 0; i < 4; i++) {
        int gm = bM + tm * 4 + i;
        if (gm >= M) continue;
#pragma unroll
        for (int j = 0; j < 4; j++) {
            int gn = bN + tn * 4 + j;
            out[(size_t)gm * C_ + gn] = acc[i][j] + bias[gn];
        }
    }
}

// ---------------------------------------------------------------------------
// launch
// inputs: 0=query (unused), 1=reference_points, 2=image_features,
//         3=lidar2img, 4=W_out, 5=b_out; output float32 (B,Q,C)
// ---------------------------------------------------------------------------
extern "C" void kernel_launch(void* const* d_in, const int* in_sizes, int n_in,
                              void* d_out, int out_size)
{
    const float* ref_pts   = (const float*)d_in[1];
    const float* feats     = (const float*)d_in[2];
    const float* lidar2img = (const float*)d_in[3];
    const float* Wm        = (const float*)d_in[4];
    const float* bias      = (const float*)d_in[5];
    float* out = (float*)d_out;

    gather_kernel<<<BQ_, C_>>>(feats, ref_pts, lidar2img);
    dim3 gg((BQ_ + BM - 1) / BM, C_ / BN);
    gemm_kernel<<<gg, 256>>>(Wm, bias, out);
}